// round 1
// baseline (speedup 1.0000x reference)
#include <cuda_runtime.h>
#include <math.h>

// ---------------------------------------------------------------------------
// GaussianSplattingCompliance
//   N_POINTS = 131072, N_G = 256
//   H[n] = (1-1e-9)*sigmoid(-10*(ks[n]-0.5)) + 1e-9
//   ks[n] = sum_b sigmoid(-10*(z[b,n]-1)) + 1e-8
//   z = sqrt(inv0*rx^2 + inv1*ry^2), rxy = R*(coords-off)/(base_scale+1e-8)
//
// Folded form: per gaussian precompute affine (A1,B1,C1,A2,B2,C2) with the
// factor K = 10*log2(e) absorbed, so that
//   u = A1*cx + B1*cy + C1, v = A2*cx + B2*cy + C2
//   e = exp2( sqrt(u*u+v*v) - K )        ( == exp(10*(z-1)) )
//   k = 1/(1+e)
// ---------------------------------------------------------------------------

#define N_POINTS 131072
#define N_G      256
#define KLOG2E   14.426950408889634f   // 10 * log2(e)

__device__ unsigned g_min_bits[2];
__device__ unsigned g_max_bits[2];
__device__ float4   g_AB[N_G];   // A1,B1,A2,B2
__device__ float2   g_C[N_G];    // C1,C2

// order-preserving float<->uint encoding (works for any sign)
__device__ __forceinline__ unsigned f_enc(float f) {
    unsigned u = __float_as_uint(f);
    return (u & 0x80000000u) ? ~u : (u | 0x80000000u);
}
__device__ __forceinline__ float f_dec(unsigned e) {
    unsigned u = (e & 0x80000000u) ? (e ^ 0x80000000u) : ~e;
    return __uint_as_float(u);
}

__device__ __forceinline__ float sigmoid_f(float x) {
    return 1.0f / (1.0f + expf(-x));
}

__global__ void gs_init_kernel() {
    if (threadIdx.x < 2) {
        g_min_bits[threadIdx.x] = 0xFFFFFFFFu;
        g_max_bits[threadIdx.x] = 0u;
    }
}

__global__ void gs_minmax_kernel(const float2* __restrict__ coords, int n) {
    float mnx = 3.4e38f, mny = 3.4e38f, mxx = -3.4e38f, mxy = -3.4e38f;
    for (int i = blockIdx.x * blockDim.x + threadIdx.x; i < n;
         i += gridDim.x * blockDim.x) {
        float2 p = coords[i];
        mnx = fminf(mnx, p.x); mny = fminf(mny, p.y);
        mxx = fmaxf(mxx, p.x); mxy = fmaxf(mxy, p.y);
    }
    #pragma unroll
    for (int o = 16; o > 0; o >>= 1) {
        mnx = fminf(mnx, __shfl_xor_sync(0xffffffffu, mnx, o));
        mny = fminf(mny, __shfl_xor_sync(0xffffffffu, mny, o));
        mxx = fmaxf(mxx, __shfl_xor_sync(0xffffffffu, mxx, o));
        mxy = fmaxf(mxy, __shfl_xor_sync(0xffffffffu, mxy, o));
    }
    if ((threadIdx.x & 31) == 0) {
        atomicMin(&g_min_bits[0], f_enc(mnx));
        atomicMin(&g_min_bits[1], f_enc(mny));
        atomicMax(&g_max_bits[0], f_enc(mxx));
        atomicMax(&g_max_bits[1], f_enc(mxy));
    }
}

__global__ void gs_params_kernel(const float* __restrict__ W_scale,
                                 const float* __restrict__ W_shape_var,
                                 const float* __restrict__ W_rotation,
                                 const float2* __restrict__ W_offsets) {
    int b = threadIdx.x;
    if (b >= N_G) return;

    float cminx = f_dec(g_min_bits[0]);
    float cminy = f_dec(g_min_bits[1]);
    float cmaxx = f_dec(g_max_bits[0]);
    float cmaxy = f_dec(g_max_bits[1]);
    // coord bounds with 0.05 * cmax padding
    float lo_x = cminx - cmaxx * 0.05f, hi_x = cmaxx + cmaxx * 0.05f;
    float lo_y = cminy - cmaxy * 0.05f, hi_y = cmaxy + cmaxy * 0.05f;

    float base_scale = (1.5f - 0.05f) * sigmoid_f(W_scale[b]) + 0.05f;
    float ratio      = (3.5f - 0.5f) * sigmoid_f(W_shape_var[b]) + 0.5f;
    const float PI_F = 3.14159265358979323846f;
    float rot        = -0.5f * PI_F + PI_F * sigmoid_f(W_rotation[b]);
    float2 wo = W_offsets[b];
    float ox = lo_x + (hi_x - lo_x) * sigmoid_f(wo.x);
    float oy = lo_y + (hi_y - lo_y) * sigmoid_f(wo.y);

    float inv_s = 1.0f / (base_scale + 1e-8f);
    float sq0 = sqrtf(1.0f / (1.0f + 1e-6f));                 // sigma0 = 1
    float sq1 = sqrtf(1.0f / (ratio * ratio + 1e-6f));        // sigma1 = ratio
    float c = cosf(rot), s = sinf(rot);

    float k0 = KLOG2E * inv_s * sq0;
    float k1 = KLOG2E * inv_s * sq1;
    float A1 =  c * k0, B1 = -s * k0;
    float A2 =  s * k1, B2 =  c * k1;
    float C1 = -(A1 * ox + B1 * oy);
    float C2 = -(A2 * ox + B2 * oy);

    g_AB[b] = make_float4(A1, B1, A2, B2);
    g_C[b]  = make_float2(C1, C2);
}

__global__ void __launch_bounds__(256)
gs_main_kernel(const float2* __restrict__ coords, float* __restrict__ out) {
    __shared__ float4 sAB[N_G];
    __shared__ float2 sC[N_G];
    int t = threadIdx.x;
    sAB[t] = g_AB[t];
    sC[t]  = g_C[t];
    __syncthreads();

    int i = blockIdx.x * 256 + t;
    float2 p = coords[i];
    float cx = p.x, cy = p.y;

    float sumA = 0.0f, sumB = 0.0f;   // two accumulators for ILP
    #pragma unroll 8
    for (int g = 0; g < N_G; g += 2) {
        {
            float4 ab = sAB[g];
            float2 cc = sC[g];
            float u = fmaf(ab.x, cx, fmaf(ab.y, cy, cc.x));
            float v = fmaf(ab.z, cx, fmaf(ab.w, cy, cc.y));
            float ss = fmaf(u, u, v * v);
            float zp;
            asm("sqrt.approx.f32 %0, %1;" : "=f"(zp) : "f"(ss));
            float e;
            asm("ex2.approx.f32 %0, %1;" : "=f"(e) : "f"(zp - KLOG2E));
            float r;
            asm("rcp.approx.f32 %0, %1;" : "=f"(r) : "f"(1.0f + e));
            sumA += r;
        }
        {
            float4 ab = sAB[g + 1];
            float2 cc = sC[g + 1];
            float u = fmaf(ab.x, cx, fmaf(ab.y, cy, cc.x));
            float v = fmaf(ab.z, cx, fmaf(ab.w, cy, cc.y));
            float ss = fmaf(u, u, v * v);
            float zp;
            asm("sqrt.approx.f32 %0, %1;" : "=f"(zp) : "f"(ss));
            float e;
            asm("ex2.approx.f32 %0, %1;" : "=f"(e) : "f"(zp - KLOG2E));
            float r;
            asm("rcp.approx.f32 %0, %1;" : "=f"(r) : "f"(1.0f + e));
            sumB += r;
        }
    }

    float ks = (sumA + sumB) + 1e-8f;
    // H = (1-1e-9)*sigmoid(-10*(ks-0.5)) + 1e-9
    float e = __expf(10.0f * (ks - 0.5f));
    float H = (1.0f - 1e-9f) / (1.0f + e) + 1e-9f;
    out[i] = H;
}

extern "C" void kernel_launch(void* const* d_in, const int* in_sizes, int n_in,
                              void* d_out, int out_size) {
    const float2* coords      = (const float2*)d_in[0];   // (131072, 2)
    const float*  W_scale     = (const float*)d_in[1];    // (256, 1)
    const float*  W_shape_var = (const float*)d_in[2];    // (256, 1)
    const float*  W_rotation  = (const float*)d_in[3];    // (256, 1)
    const float2* W_offsets   = (const float2*)d_in[4];   // (256, 2)
    float* out = (float*)d_out;

    gs_init_kernel<<<1, 32>>>();
    gs_minmax_kernel<<<256, 256>>>(coords, N_POINTS);
    gs_params_kernel<<<1, N_G>>>(W_scale, W_shape_var, W_rotation, W_offsets);
    gs_main_kernel<<<N_POINTS / 256, 256>>>(coords, out);
}

// round 2
// speedup vs baseline: 1.4068x; 1.4068x over previous
#include <cuda_runtime.h>
#include <math.h>

// ---------------------------------------------------------------------------
// GaussianSplattingCompliance: N_POINTS=131072, N_G=256
//   kernel  = sigmoid(-10(z-1)) = 0.5 - 0.5*tanh(5(z-1))
//   z       = |R*(c-off)| scaled by inv_cov/base_scale
// Per gaussian precompute affine (A1,B1,C1,A2,B2,C2) with factor 5 absorbed:
//   u = A1*cx+B1*cy+C1, v = A2*cx+B2*cy+C2,  sqrt(u^2+v^2) == 5z
//   t = tanh.approx(sqrt(uu+vv) - 5),  ks = 128 - 0.5*sum(t) + 1e-8
// ---------------------------------------------------------------------------

#define N_POINTS 131072
#define N_G      256
#define PRE_BLOCKS 256

__device__ unsigned g_enc[4];      // enc(max x), enc(max y), enc(max -x), enc(max -y)
__device__ unsigned g_count;
__device__ float4   g_AB[N_G];     // A1,B1,A2,B2
__device__ float2   g_C[N_G];      // C1,C2

// order-preserving float->uint encoding; enc value 0 is below every float's
// encoding (acts as -inf identity for atomicMax on zero-initialized scratch)
__device__ __forceinline__ unsigned f_enc(float f) {
    unsigned u = __float_as_uint(f);
    return (u & 0x80000000u) ? ~u : (u | 0x80000000u);
}
__device__ __forceinline__ float f_dec(unsigned e) {
    unsigned u = (e & 0x80000000u) ? (e ^ 0x80000000u) : ~e;
    return __uint_as_float(u);
}
__device__ __forceinline__ float sigmoid_f(float x) {
    return 1.0f / (1.0f + expf(-x));
}

// Fused: coords min/max reduction + (last block) per-gaussian param precompute
// + scratch reset for next graph replay. 256 blocks x 256 threads, one float4
// (= 2 points) per thread.
__global__ void __launch_bounds__(256)
gs_pre_kernel(const float4* __restrict__ coords4,
              const float*  __restrict__ W_scale,
              const float*  __restrict__ W_shape_var,
              const float*  __restrict__ W_rotation,
              const float2* __restrict__ W_offsets) {
    __shared__ float s_red[8][4];
    __shared__ int   s_last;
    int tid = threadIdx.x;

    float4 q = coords4[blockIdx.x * 256 + tid];   // points (x,y),(z,w)
    float mxx = fmaxf(q.x, q.z), mxy = fmaxf(q.y, q.w);
    float mnx = fminf(q.x, q.z), mny = fminf(q.y, q.w);
    float nmx = -mnx, nmy = -mny;                 // track max(-x) = -min(x)

    #pragma unroll
    for (int o = 16; o > 0; o >>= 1) {
        mxx = fmaxf(mxx, __shfl_xor_sync(0xffffffffu, mxx, o));
        mxy = fmaxf(mxy, __shfl_xor_sync(0xffffffffu, mxy, o));
        nmx = fmaxf(nmx, __shfl_xor_sync(0xffffffffu, nmx, o));
        nmy = fmaxf(nmy, __shfl_xor_sync(0xffffffffu, nmy, o));
    }
    int wid = tid >> 5, lid = tid & 31;
    if (lid == 0) {
        s_red[wid][0] = mxx; s_red[wid][1] = mxy;
        s_red[wid][2] = nmx; s_red[wid][3] = nmy;
    }
    __syncthreads();
    if (tid == 0) {
        float a = s_red[0][0], b = s_red[0][1], c = s_red[0][2], d = s_red[0][3];
        #pragma unroll
        for (int w = 1; w < 8; w++) {
            a = fmaxf(a, s_red[w][0]); b = fmaxf(b, s_red[w][1]);
            c = fmaxf(c, s_red[w][2]); d = fmaxf(d, s_red[w][3]);
        }
        atomicMax(&g_enc[0], f_enc(a));
        atomicMax(&g_enc[1], f_enc(b));
        atomicMax(&g_enc[2], f_enc(c));
        atomicMax(&g_enc[3], f_enc(d));
        __threadfence();
        unsigned done = atomicAdd(&g_count, 1u);
        s_last = (done == PRE_BLOCKS - 1) ? 1 : 0;
    }
    __syncthreads();
    if (!s_last) return;

    // Last block: compute all 256 gaussian params (one per thread)
    float cmaxx = f_dec(atomicMax(&g_enc[0], 0u));
    float cmaxy = f_dec(atomicMax(&g_enc[1], 0u));
    float cminx = -f_dec(atomicMax(&g_enc[2], 0u));
    float cminy = -f_dec(atomicMax(&g_enc[3], 0u));

    float lo_x = cminx - cmaxx * 0.05f, hi_x = cmaxx + cmaxx * 0.05f;
    float lo_y = cminy - cmaxy * 0.05f, hi_y = cmaxy + cmaxy * 0.05f;

    int b = tid;
    float base_scale = (1.5f - 0.05f) * sigmoid_f(W_scale[b]) + 0.05f;
    float ratio      = (3.5f - 0.5f) * sigmoid_f(W_shape_var[b]) + 0.5f;
    const float PI_F = 3.14159265358979323846f;
    float rot        = -0.5f * PI_F + PI_F * sigmoid_f(W_rotation[b]);
    float2 wo = W_offsets[b];
    float ox = lo_x + (hi_x - lo_x) * sigmoid_f(wo.x);
    float oy = lo_y + (hi_y - lo_y) * sigmoid_f(wo.y);

    float inv_s = 1.0f / (base_scale + 1e-8f);
    float sq0 = sqrtf(1.0f / (1.0f + 1e-6f));
    float sq1 = sqrtf(1.0f / (ratio * ratio + 1e-6f));
    float c = cosf(rot), s = sinf(rot);

    float k0 = 5.0f * inv_s * sq0;        // absorb tanh slope 5
    float k1 = 5.0f * inv_s * sq1;
    float A1 =  c * k0, B1 = -s * k0;
    float A2 =  s * k1, B2 =  c * k1;
    float C1 = -(A1 * ox + B1 * oy);
    float C2 = -(A2 * ox + B2 * oy);

    g_AB[b] = make_float4(A1, B1, A2, B2);
    g_C[b]  = make_float2(C1, C2);

    // Reset scratch for next graph replay (state-restoring; deterministic)
    if (tid < 4) g_enc[tid] = 0u;
    if (tid == 0) g_count = 0u;
}

__global__ void __launch_bounds__(128)
gs_main_kernel(const float2* __restrict__ coords, float* __restrict__ out) {
    __shared__ float4 sAB[N_G];
    __shared__ float2 sC[N_G];
    int t = threadIdx.x;
    sAB[t]       = g_AB[t];
    sAB[t + 128] = g_AB[t + 128];
    sC[t]        = g_C[t];
    sC[t + 128]  = g_C[t + 128];
    __syncthreads();

    int i = blockIdx.x * 128 + t;
    float2 p = coords[i];
    float cx = p.x, cy = p.y;

    float sumA = 0.0f, sumB = 0.0f;
    #pragma unroll 8
    for (int g = 0; g < N_G; g += 2) {
        {
            float4 ab = sAB[g];
            float2 cc = sC[g];
            float u = fmaf(ab.x, cx, fmaf(ab.y, cy, cc.x));
            float v = fmaf(ab.z, cx, fmaf(ab.w, cy, cc.y));
            float ss = fmaf(u, u, v * v);
            float zp;
            asm("sqrt.approx.f32 %0, %1;" : "=f"(zp) : "f"(ss));
            float th;
            asm("tanh.approx.f32 %0, %1;" : "=f"(th) : "f"(zp - 5.0f));
            sumA += th;
        }
        {
            float4 ab = sAB[g + 1];
            float2 cc = sC[g + 1];
            float u = fmaf(ab.x, cx, fmaf(ab.y, cy, cc.x));
            float v = fmaf(ab.z, cx, fmaf(ab.w, cy, cc.y));
            float ss = fmaf(u, u, v * v);
            float zp;
            asm("sqrt.approx.f32 %0, %1;" : "=f"(zp) : "f"(ss));
            float th;
            asm("tanh.approx.f32 %0, %1;" : "=f"(th) : "f"(zp - 5.0f));
            sumB += th;
        }
    }

    // ks = sum(0.5 - 0.5*t) + 1e-8 = 128 - 0.5*sum(t) + 1e-8
    float ks = fmaf(-0.5f, sumA + sumB, 128.0f) + 1e-8f;
    float e = __expf(10.0f * (ks - 0.5f));
    float H = (1.0f - 1e-9f) / (1.0f + e) + 1e-9f;
    out[i] = H;
}

extern "C" void kernel_launch(void* const* d_in, const int* in_sizes, int n_in,
                              void* d_out, int out_size) {
    const float4* coords4     = (const float4*)d_in[0];   // (131072, 2) as 65536 float4
    const float*  W_scale     = (const float*)d_in[1];    // (256, 1)
    const float*  W_shape_var = (const float*)d_in[2];    // (256, 1)
    const float*  W_rotation  = (const float*)d_in[3];    // (256, 1)
    const float2* W_offsets   = (const float2*)d_in[4];   // (256, 2)
    float* out = (float*)d_out;

    gs_pre_kernel<<<PRE_BLOCKS, 256>>>(coords4, W_scale, W_shape_var,
                                       W_rotation, W_offsets);
    gs_main_kernel<<<N_POINTS / 128, 128>>>((const float2*)d_in[0], out);
}